// round 7
// baseline (speedup 1.0000x reference)
#include <cuda_runtime.h>
#include <cuda_bf16.h>

// ---------------------------------------------------------------------------
// Policy_73916387164829: fused RL policy network, fp32, sparse conv1.
//
// Pipeline per sample:
//   scatter 200 tokens -> dense box[22][11][11] (smem, DETERMINISTIC last-
//   token-wins via atomicMax on packed (m<<8|val) keys)
//   compact nonzeros -> 9 per-(oy,ox) contribution lists
//   conv1 (sparse, 5x5 s3): per-position lists x 128 oc, LDG.128 weight vecs
//   conv2 (dense GEMV 1152x128), fc (128->256), self (22->256), 3 heads (512->20)
// Block = 256 threads, NS=16 samples/block. All weights pre-transposed to
// oc-minor layouts by a prep kernel into __device__ scratch.
// ---------------------------------------------------------------------------

#define NS 16
#define NTHR 256
#define CAP 128          // per-position list capacity (mean ~40, 14 sigma margin)

// ---- device scratch (transposed weights) ----------------------------------
__device__ __align__(16) float g_w1t[550 * 128];     // [c*25+kx*5+ky][oc]
__device__ __align__(16) float g_w2q[288 * 512];     // [k/4][oc][k%4], k=ic*9+a*3+b
__device__ __align__(16) float g_fcwq[32 * 1024];    // [ic/4][row][ic%4]
__device__ __align__(16) float g_selfwt[22 * 256];   // [c][row]

__constant__ float c_invmax[22] = {
    1.f/9, 1.f, 1.f, 1.f/10, 1.f/3, 1.f/254, 1.f, 1.f, 1.f/235, 1.f/8, 1.f/9,
    1.f/250, 1.f/29, 1.f, 1.f, 1.f/8, 1.f, 1.f, 1.f/6, 1.f/3, 1.f, 1.f/2 };

// input row ix -> output rows oy (stride 3, kernel 5): (oy, kx=ix-3*oy)
__constant__ int c_tabn[11]     = {1,1,1,2,2,1,2,2,1,1,1};
__constant__ int c_taboy[11][2] = {{0,0},{0,0},{0,0},{0,1},{0,1},{1,0},
                                   {1,2},{1,2},{2,0},{2,0},{2,0}};
__constant__ int c_tabk[11][2]  = {{0,0},{1,0},{2,0},{3,0},{4,1},{2,0},
                                   {3,0},{4,1},{2,0},{3,0},{4,0}};

// ---- weight transpose prekernel -------------------------------------------
__global__ void prep_kernel(const float* __restrict__ w1,
                            const float* __restrict__ w2,
                            const float* __restrict__ fcw,
                            const float* __restrict__ sw) {
    int i = blockIdx.x * blockDim.x + threadIdx.x;
    int stride = gridDim.x * blockDim.x;
    for (int j = i; j < 70400; j += stride) {          // conv1_w [128][22][5][5]
        int oc = j / 550, widx = j - oc * 550;
        g_w1t[widx * 128 + oc] = w1[j];
    }
    for (int j = i; j < 147456; j += stride) {         // conv2_w [128][128][3][3]
        int oc = j / 1152, k = j - oc * 1152;          // k = ic*9 + a*3 + b
        g_w2q[(k >> 2) * 512 + oc * 4 + (k & 3)] = w2[j];
    }
    for (int j = i; j < 32768; j += stride) {          // fc_w [256][128]
        int r = j >> 7, ic = j & 127;
        g_fcwq[(ic >> 2) * 1024 + r * 4 + (ic & 3)] = fcw[j];
    }
    for (int j = i; j < 5632; j += stride) {           // self_w [256][22]
        int r = j / 22, c = j - r * 22;
        g_selfwt[c * 256 + r] = sw[j];
    }
}

// ---- smem layout (floats) --------------------------------------------------
// part   [0,     9216)   8 warps x 1152 partials (int box[2662] aliased here)
// h1s    [9216,  27648)  16 x 1152 conv1 outputs (hid[16x512] aliased after conv2)
// h2s    [27648, 29696)  16 x 128
// selfcol[29696, 30048)  16 x 22
// lidx   [30048, 31200)  9 x 128 (int)
// lval   [31200, 32352)  9 x 128
// cnt    [32352, 32368)
#define SMEM_FLOATS 32368
#define SMEM_BYTES  (SMEM_FLOATS * 4)

__global__ __launch_bounds__(NTHR, 1)
void policy_main(const int* __restrict__ obs,
                 const float* __restrict__ c1b, const float* __restrict__ c2b,
                 const float* __restrict__ fcb, const float* __restrict__ sb,
                 const float* __restrict__ a0w, const float* __restrict__ a0b,
                 const float* __restrict__ a1w, const float* __restrict__ a1b,
                 const float* __restrict__ vw,  const float* __restrict__ vb,
                 float* __restrict__ out, int nb) {
    extern __shared__ float sm[];
    float* part    = sm;
    int*   boxi    = (int*)sm;         // alias (dead before part is written)
    float* h1s     = sm + 9216;
    float* hid     = sm + 9216;        // alias (h1s dead after conv2)
    float* h2s     = sm + 27648;
    float* selfcol = sm + 29696;
    int*   lidx    = (int*)(sm + 30048);
    float* lval    = sm + 31200;
    int*   cnt     = (int*)(sm + 32352);

    const int t    = threadIdx.x;
    const int lane = t & 31;
    const int grp  = t >> 5;           // warp id = entry-split group (8-way)
    const int b0   = blockIdx.x * NS;

    // ================= per-sample: scatter + compact + sparse conv1 ========
    for (int s = 0; s < NS; ++s) {
        // zero box + counters
        for (int e = t; e < 2662; e += NTHR) boxi[e] = 0;
        if (t < 9) cnt[t] = 0;
        __syncthreads();

        // scatter tokens: DETERMINISTIC last-token-wins. Pack (m<<8 | val);
        // atomicMax keeps the highest token index m (reference applies scatter
        // updates serially in token order, so the last duplicate wins).
        // Empty cell packed==0 decodes to val 0 == reference background.
        if (b0 + s < nb) {
            const int* ob = obs + (long long)(b0 + s) * 600;
            for (int m = t; m < 200; m += NTHR) {
                int cc = ob[3 * m], aa = ob[3 * m + 1], vv = ob[3 * m + 2];
                if (cc == 255) cc = 0;
                if (aa == 255) aa = 0;
                if (vv == 255) vv = 0;
                int x = (cc >> 4) & 15, y = cc & 15;
                if (aa < 22 && x < 11 && y < 11)
                    atomicMax(&boxi[aa * 121 + x * 11 + y], (m << 8) | (vv & 255));
            }
        }
        __syncthreads();

        // self-branch column (cell (5,5) of each layer)
        if (t < 22)
            selfcol[s * 22 + t] =
                (float)(boxi[t * 121 + 60] & 255) * c_invmax[t];

        // compact nonzero cells into 9 per-output-position lists
        for (int e = t; e < 2662; e += NTHR) {
            int pk = boxi[e] & 255;
            if (pk != 0) {
                int c = e / 121, r = e - c * 121;
                float v = (float)pk * c_invmax[c];
                int x = r / 11, y = r - x * 11;
                int nx = c_tabn[x], ny = c_tabn[y];
                for (int a = 0; a < nx; ++a)
                    for (int b = 0; b < ny; ++b) {
                        int pos  = c_taboy[x][a] * 3 + c_taboy[y][b];
                        int widx = (c * 5 + c_tabk[x][a]) * 5 + c_tabk[y][b];
                        int i = atomicAdd(&cnt[pos], 1);
                        if (i < CAP) {
                            lidx[(pos << 7) + i] = widx;
                            lval[(pos << 7) + i] = v;
                        }
                    }
            }
        }
        __syncthreads();

        // sparse conv1: lane = oc quad (4 oc via LDG.128), warp = entry split
        #pragma unroll
        for (int pos = 0; pos < 9; ++pos) {
            int n = cnt[pos]; if (n > CAP) n = CAP;
            const int*   li = lidx + (pos << 7);
            const float* lv = lval + (pos << 7);
            float4 a = make_float4(0.f, 0.f, 0.f, 0.f);
            #pragma unroll 2
            for (int i = grp; i < n; i += 8) {
                int widx = li[i];
                float v  = lv[i];
                float4 w = *reinterpret_cast<const float4*>(
                               g_w1t + widx * 128 + (lane << 2));
                a.x = fmaf(v, w.x, a.x);
                a.y = fmaf(v, w.y, a.y);
                a.z = fmaf(v, w.z, a.z);
                a.w = fmaf(v, w.w, a.w);
            }
            // stage partial: part[grp][pos][oc] (conflict-free STS.128)
            *reinterpret_cast<float4*>(part + grp * 1152 + (pos << 7) + (lane << 2)) = a;
        }
        __syncthreads();

        // reduce 8 partials + bias + relu -> h1s[s][ic*9+pos]
        for (int ii = t; ii < 1152; ii += NTHR) {
            int pos = ii >> 7, ic = ii & 127;
            float ssum = c1b[ic];
            #pragma unroll
            for (int g = 0; g < 8; ++g) ssum += part[g * 1152 + ii];
            h1s[s * 1152 + ic * 9 + pos] = fmaxf(ssum, 0.f);
        }
        __syncthreads();
    }

    // ================= conv2: 1152 -> 128, 8 samples per thread ============
    {
        const int oc = t & 127, sg = t >> 7;
        float acc2[8] = {0,0,0,0,0,0,0,0};
        const float* h1base = h1s + sg * 8 * 1152;
        for (int kq = 0; kq < 288; ++kq) {
            float4 w = *reinterpret_cast<const float4*>(g_w2q + kq * 512 + oc * 4);
            #pragma unroll
            for (int j = 0; j < 8; ++j) {
                float4 h = *reinterpret_cast<const float4*>(h1base + j * 1152 + kq * 4);
                acc2[j] = fmaf(h.x, w.x, acc2[j]);
                acc2[j] = fmaf(h.y, w.y, acc2[j]);
                acc2[j] = fmaf(h.z, w.z, acc2[j]);
                acc2[j] = fmaf(h.w, w.w, acc2[j]);
            }
        }
        float b = c2b[oc];
        #pragma unroll
        for (int j = 0; j < 8; ++j)
            h2s[(sg * 8 + j) * 128 + oc] = fmaxf(acc2[j] + b, 0.f);
    }
    __syncthreads();

    // ================= fc (128->256) + self (22->256) -> hid[16][512] ======
    {
        // thread t = output row (0..255), all 16 samples in registers
        float accf[NS];
        #pragma unroll
        for (int j = 0; j < NS; ++j) accf[j] = 0.f;
        for (int iq = 0; iq < 32; ++iq) {
            float4 w = *reinterpret_cast<const float4*>(g_fcwq + iq * 1024 + t * 4);
            #pragma unroll
            for (int j = 0; j < NS; ++j) {
                float4 h = *reinterpret_cast<const float4*>(h2s + j * 128 + iq * 4);
                accf[j] = fmaf(h.x, w.x, accf[j]);
                accf[j] = fmaf(h.y, w.y, accf[j]);
                accf[j] = fmaf(h.z, w.z, accf[j]);
                accf[j] = fmaf(h.w, w.w, accf[j]);
            }
        }
        float accs[NS];
        #pragma unroll
        for (int j = 0; j < NS; ++j) accs[j] = 0.f;
        for (int c = 0; c < 22; ++c) {
            float w = g_selfwt[c * 256 + t];
            #pragma unroll
            for (int j = 0; j < NS; ++j)
                accs[j] = fmaf(selfcol[j * 22 + c], w, accs[j]);
        }
        float bf = fcb[t], bs = sb[t];
        #pragma unroll
        for (int j = 0; j < NS; ++j) {
            hid[j * 512 + t]       = fmaxf(accs[j] + bs, 0.f);  // self_f
            hid[j * 512 + 256 + t] = fmaxf(accf[j] + bf, 0.f);  // cnn_f
        }
    }
    __syncthreads();

    // ================= heads: 20 x dot(512) per sample =====================
    {
        long long o9  = (long long)nb * 9;
        long long o19 = (long long)nb * 19;
        for (int o = grp; o < 20; o += 8) {
            const float* hw; float hb;
            if (o < 9)       { hw = a0w + o * 512;        hb = a0b[o]; }
            else if (o < 19) { hw = a1w + (o - 9) * 512;  hb = a1b[o - 9]; }
            else             { hw = vw;                   hb = vb[0]; }
            for (int j = 0; j < NS; ++j) {
                float p = 0.f;
                const float* hj = hid + j * 512;
                #pragma unroll
                for (int k = 0; k < 16; ++k)
                    p = fmaf(hw[lane + 32 * k], hj[lane + 32 * k], p);
                p += __shfl_xor_sync(0xffffffffu, p, 16);
                p += __shfl_xor_sync(0xffffffffu, p, 8);
                p += __shfl_xor_sync(0xffffffffu, p, 4);
                p += __shfl_xor_sync(0xffffffffu, p, 2);
                p += __shfl_xor_sync(0xffffffffu, p, 1);
                if (lane == 0 && b0 + j < nb) {
                    long long b = b0 + j;
                    float r = p + hb;
                    if (o < 9)       out[b * 9 + o] = r;
                    else if (o < 19) out[o9 + b * 10 + (o - 9)] = r;
                    else             out[o19 + b] = r;
                }
            }
        }
    }
}

// ---------------------------------------------------------------------------
extern "C" void kernel_launch(void* const* d_in, const int* in_sizes, int n_in,
                              void* d_out, int out_size) {
    const int*   obs = (const int*)d_in[0];
    const float* c1w = (const float*)d_in[1];
    const float* c1b = (const float*)d_in[2];
    const float* c2w = (const float*)d_in[3];
    const float* c2b = (const float*)d_in[4];
    const float* fcw = (const float*)d_in[5];
    const float* fcb = (const float*)d_in[6];
    const float* sw  = (const float*)d_in[7];
    const float* sb  = (const float*)d_in[8];
    const float* a0w = (const float*)d_in[9];
    const float* a0b = (const float*)d_in[10];
    const float* a1w = (const float*)d_in[11];
    const float* a1b = (const float*)d_in[12];
    const float* vw  = (const float*)d_in[13];
    const float* vb  = (const float*)d_in[14];

    int nb = in_sizes[0] / 600;   // 16384

    cudaFuncSetAttribute(policy_main,
                         cudaFuncAttributeMaxDynamicSharedMemorySize, SMEM_BYTES);

    prep_kernel<<<256, 256>>>(c1w, c2w, fcw, sw);

    int grid = (nb + NS - 1) / NS;
    policy_main<<<grid, NTHR, SMEM_BYTES>>>(obs, c1b, c2b, fcb, sb,
                                            a0w, a0b, a1w, a1b, vw, vb,
                                            (float*)d_out, nb);
}

// round 17
// speedup vs baseline: 2.3218x; 2.3218x over previous
#include <cuda_runtime.h>
#include <cuda_bf16.h>

// ---------------------------------------------------------------------------
// Policy_73916387164829 — two-kernel split (R7: was 1594us, occ 12%, all pipes
// idle -> kill serialization).
//   prep:    transpose weights to oc-minor layouts (device scratch)
//   kernelA: block=128, 1 sample/block. scatter 200 tokens -> smem box
//            (atomicMax (m<<8)|val = deterministic last-token-wins), winner
//            re-check over tokens (no 2662-cell scan), sparse conv1 -> g_h1.
//            smem ~20KB -> ~11 CTA/SM.
//   kernelB: block=256, 16 samples/block. h1 tile -> smem, conv2 (LDS
//            broadcast h + coalesced LDG weights), fc+self -> hidden, heads.
// ---------------------------------------------------------------------------

#define MAXB 16384

// ---- device scratch --------------------------------------------------------
__device__ __align__(16) float g_w1t[550 * 128];     // [c*25+kx*5+ky][oc]
__device__ __align__(16) float g_w2q[288 * 512];     // [k/4][oc][k%4], k=ic*9+pos
__device__ __align__(16) float g_fcwq[32 * 1024];    // [ic/4][row][ic%4]
__device__ __align__(16) float g_selfwt[22 * 256];   // [c][row]
__device__ __align__(16) float g_h1[(size_t)MAXB * 1152];   // conv1 out
__device__ __align__(16) float g_selfg[(size_t)MAXB * 22];  // self column

__constant__ float c_invmax[22] = {
    1.f/9, 1.f, 1.f, 1.f/10, 1.f/3, 1.f/254, 1.f, 1.f, 1.f/235, 1.f/8, 1.f/9,
    1.f/250, 1.f/29, 1.f, 1.f, 1.f/8, 1.f, 1.f, 1.f/6, 1.f/3, 1.f, 1.f/2 };

// input row ix -> output rows oy (stride 3, kernel 5): (oy, kx=ix-3*oy)
__constant__ int c_tabn[11]     = {1,1,1,2,2,1,2,2,1,1,1};
__constant__ int c_taboy[11][2] = {{0,0},{0,0},{0,0},{0,1},{0,1},{1,0},
                                   {1,2},{1,2},{2,0},{2,0},{2,0}};
__constant__ int c_tabk[11][2]  = {{0,0},{1,0},{2,0},{3,0},{4,1},{2,0},
                                   {3,0},{4,1},{2,0},{3,0},{4,0}};

// ---- weight transpose prekernel -------------------------------------------
__global__ void prep_kernel(const float* __restrict__ w1,
                            const float* __restrict__ w2,
                            const float* __restrict__ fcw,
                            const float* __restrict__ sw) {
    int i = blockIdx.x * blockDim.x + threadIdx.x;
    int stride = gridDim.x * blockDim.x;
    for (int j = i; j < 70400; j += stride) {          // conv1_w [128][22][5][5]
        int oc = j / 550, widx = j - oc * 550;
        g_w1t[widx * 128 + oc] = w1[j];
    }
    for (int j = i; j < 147456; j += stride) {         // conv2_w [128][128][3][3]
        int oc = j / 1152, k = j - oc * 1152;          // k = ic*9 + pos
        g_w2q[(k >> 2) * 512 + oc * 4 + (k & 3)] = w2[j];
    }
    for (int j = i; j < 32768; j += stride) {          // fc_w [256][128]
        int r = j >> 7, ic = j & 127;
        g_fcwq[(ic >> 2) * 1024 + r * 4 + (ic & 3)] = fcw[j];
    }
    for (int j = i; j < 5632; j += stride) {           // self_w [256][22]
        int r = j / 22, c = j - r * 22;
        g_selfwt[c * 256 + r] = sw[j];
    }
}

// ===========================================================================
// Kernel A: scatter + sparse conv1, one sample per 128-thread block
// ===========================================================================
#define A_THR 128
#define A_CAP 256        // >= 200 tokens, cannot overflow

__global__ __launch_bounds__(A_THR)
void conv1_kernel(const int* __restrict__ obs,
                  const float* __restrict__ c1b, int nb) {
    __shared__ int boxi[2662];
    __shared__ int lst[9 * A_CAP];   // (widx<<13)|(chan<<8)|val
    __shared__ int cnt[9];

    const int b = blockIdx.x;
    const int t = threadIdx.x;
    if (b >= nb) return;

    for (int e = t; e < 2662; e += A_THR) boxi[e] = 0;
    if (t < 9) cnt[t] = 0;
    __syncthreads();

    const int* ob = obs + (size_t)b * 600;

    // scatter: deterministic last-token-wins via key (m<<8)|val
    for (int m = t; m < 200; m += A_THR) {
        int cc = ob[3 * m], aa = ob[3 * m + 1], vv = ob[3 * m + 2];
        if (cc == 255) cc = 0;
        if (aa == 255) aa = 0;
        if (vv == 255) vv = 0;
        int x = (cc >> 4) & 15, y = cc & 15;
        if (aa < 22 && x < 11 && y < 11)
            atomicMax(&boxi[aa * 121 + x * 11 + y], (m << 8) | (vv & 255));
    }
    __syncthreads();

    // self-branch column (cell (5,5) of each layer)
    if (t < 22)
        g_selfg[(size_t)b * 22 + t] =
            (float)(boxi[t * 121 + 60] & 255) * c_invmax[t];

    // winner pass: token m is the cell's representative iff its key survived
    // (vv==0 winners contribute nothing to the conv and are skipped)
    for (int m = t; m < 200; m += A_THR) {
        int cc = ob[3 * m], aa = ob[3 * m + 1], vv = ob[3 * m + 2];
        if (cc == 255) cc = 0;
        if (aa == 255) aa = 0;
        if (vv == 255) vv = 0;
        int x = (cc >> 4) & 15, y = cc & 15;
        if (aa < 22 && x < 11 && y < 11 && vv != 0 &&
            boxi[aa * 121 + x * 11 + y] == ((m << 8) | (vv & 255))) {
            int nx = c_tabn[x], ny = c_tabn[y];
            for (int a = 0; a < nx; ++a)
                for (int bb = 0; bb < ny; ++bb) {
                    int pos  = c_taboy[x][a] * 3 + c_taboy[y][bb];
                    int widx = (aa * 5 + c_tabk[x][a]) * 5 + c_tabk[y][bb];
                    int i = atomicAdd(&cnt[pos], 1);
                    lst[pos * A_CAP + i] = (widx << 13) | (aa << 8) | (vv & 255);
                }
        }
    }
    __syncthreads();

    // sparse conv1: thread t = output channel; coalesced 512B weight rows
    const float bias = c1b[t];
    float* h1o = g_h1 + (size_t)b * 1152 + t * 9;
    #pragma unroll
    for (int pos = 0; pos < 9; ++pos) {
        int n = cnt[pos];
        const int* lp = lst + pos * A_CAP;
        float acc = 0.f;
        for (int i = 0; i < n; ++i) {
            int e    = lp[i];
            int widx = e >> 13;
            int ch   = (e >> 8) & 31;
            float v  = (float)(e & 255) * c_invmax[ch];
            acc = fmaf(v, g_w1t[widx * 128 + t], acc);
        }
        h1o[pos] = fmaxf(acc + bias, 0.f);
    }
}

// ===========================================================================
// Kernel B: conv2 + fc + self + heads, 16 samples per 256-thread block
// ===========================================================================
#define B_THR 256
#define BNS 16

// smem (floats): h1t[16*1152]=18432 (hid[16*512] aliases it after conv2),
//                h2s[16*128]=2048 @18432, selfc[16*22]=352 @20480
#define B_SMEM_FLOATS 20832
#define B_SMEM_BYTES  (B_SMEM_FLOATS * 4)

__global__ __launch_bounds__(B_THR)
void policy_tail(const float* __restrict__ c2b,
                 const float* __restrict__ fcb, const float* __restrict__ sb,
                 const float* __restrict__ a0w, const float* __restrict__ a0b,
                 const float* __restrict__ a1w, const float* __restrict__ a1b,
                 const float* __restrict__ vw,  const float* __restrict__ vb,
                 float* __restrict__ out, int nb) {
    extern __shared__ float sm[];
    float* h1t   = sm;            // 16 x 1152
    float* hid   = sm;            // alias (h1t dead after conv2)
    float* h2s   = sm + 18432;    // 16 x 128
    float* selfc = sm + 20480;    // 16 x 22

    const int t    = threadIdx.x;
    const int lane = t & 31;
    const int grp  = t >> 5;
    const int b0   = blockIdx.x * BNS;

    // ---- stage h1 tile (coalesced float4) + self columns ----
    {
        float4* dst = (float4*)h1t;
        for (int i = t; i < BNS * 288; i += B_THR) {
            int j = i / 288, w = i - j * 288;
            float4 v = make_float4(0.f, 0.f, 0.f, 0.f);
            if (b0 + j < nb)
                v = ((const float4*)(g_h1 + (size_t)(b0 + j) * 1152))[w];
            dst[i] = v;
        }
        for (int i = t; i < BNS * 22; i += B_THR) {
            int j = i / 22, c = i - j * 22;
            selfc[i] = (b0 + j < nb) ? g_selfg[(size_t)(b0 + j) * 22 + c] : 0.f;
        }
    }
    __syncthreads();

    // ---- conv2: 1152 -> 128, 8 samples per thread, h via LDS broadcast ----
    {
        const int oc = t & 127, sg = t >> 7;
        float acc2[8] = {0,0,0,0,0,0,0,0};
        const float* hb = h1t + sg * 8 * 1152;
        for (int kq = 0; kq < 288; ++kq) {
            float4 w = *reinterpret_cast<const float4*>(g_w2q + kq * 512 + oc * 4);
            #pragma unroll
            for (int j = 0; j < 8; ++j) {
                float4 h = *reinterpret_cast<const float4*>(hb + j * 1152 + kq * 4);
                acc2[j] = fmaf(h.x, w.x, acc2[j]);
                acc2[j] = fmaf(h.y, w.y, acc2[j]);
                acc2[j] = fmaf(h.z, w.z, acc2[j]);
                acc2[j] = fmaf(h.w, w.w, acc2[j]);
            }
        }
        float bias = c2b[oc];
        #pragma unroll
        for (int j = 0; j < 8; ++j)
            h2s[(sg * 8 + j) * 128 + oc] = fmaxf(acc2[j] + bias, 0.f);
    }
    __syncthreads();

    // ---- fc (128->256) + self (22->256) -> hid[16][512] ----
    {
        float accf[BNS];
        #pragma unroll
        for (int j = 0; j < BNS; ++j) accf[j] = 0.f;
        for (int iq = 0; iq < 32; ++iq) {
            float4 w = *reinterpret_cast<const float4*>(g_fcwq + iq * 1024 + t * 4);
            #pragma unroll
            for (int j = 0; j < BNS; ++j) {
                float4 h = *reinterpret_cast<const float4*>(h2s + j * 128 + iq * 4);
                accf[j] = fmaf(h.x, w.x, accf[j]);
                accf[j] = fmaf(h.y, w.y, accf[j]);
                accf[j] = fmaf(h.z, w.z, accf[j]);
                accf[j] = fmaf(h.w, w.w, accf[j]);
            }
        }
        float accs[BNS];
        #pragma unroll
        for (int j = 0; j < BNS; ++j) accs[j] = 0.f;
        for (int c = 0; c < 22; ++c) {
            float w = g_selfwt[c * 256 + t];
            #pragma unroll
            for (int j = 0; j < BNS; ++j)
                accs[j] = fmaf(selfc[j * 22 + c], w, accs[j]);
        }
        float bf = fcb[t], bs = sb[t];
        __syncthreads();   // h1t fully consumed before hid overwrite
        #pragma unroll
        for (int j = 0; j < BNS; ++j) {
            hid[j * 512 + t]       = fmaxf(accs[j] + bs, 0.f);  // self_f
            hid[j * 512 + 256 + t] = fmaxf(accf[j] + bf, 0.f);  // cnn_f
        }
    }
    __syncthreads();

    // ---- heads: 20 x dot(512) per sample ----
    {
        long long o9  = (long long)nb * 9;
        long long o19 = (long long)nb * 19;
        for (int o = grp; o < 20; o += 8) {
            const float* hw; float hb;
            if (o < 9)       { hw = a0w + o * 512;        hb = a0b[o]; }
            else if (o < 19) { hw = a1w + (o - 9) * 512;  hb = a1b[o - 9]; }
            else             { hw = vw;                   hb = vb[0]; }
            for (int j = 0; j < BNS; ++j) {
                float p = 0.f;
                const float* hj = hid + j * 512;
                #pragma unroll
                for (int k = 0; k < 16; ++k)
                    p = fmaf(hw[lane + 32 * k], hj[lane + 32 * k], p);
                p += __shfl_xor_sync(0xffffffffu, p, 16);
                p += __shfl_xor_sync(0xffffffffu, p, 8);
                p += __shfl_xor_sync(0xffffffffu, p, 4);
                p += __shfl_xor_sync(0xffffffffu, p, 2);
                p += __shfl_xor_sync(0xffffffffu, p, 1);
                if (lane == 0 && b0 + j < nb) {
                    long long b = b0 + j;
                    float r = p + hb;
                    if (o < 9)       out[b * 9 + o] = r;
                    else if (o < 19) out[o9 + b * 10 + (o - 9)] = r;
                    else             out[o19 + b] = r;
                }
            }
        }
    }
}

// ---------------------------------------------------------------------------
extern "C" void kernel_launch(void* const* d_in, const int* in_sizes, int n_in,
                              void* d_out, int out_size) {
    const int*   obs = (const int*)d_in[0];
    const float* c1w = (const float*)d_in[1];
    const float* c1b = (const float*)d_in[2];
    const float* c2w = (const float*)d_in[3];
    const float* c2b = (const float*)d_in[4];
    const float* fcw = (const float*)d_in[5];
    const float* fcb = (const float*)d_in[6];
    const float* sw  = (const float*)d_in[7];
    const float* sb  = (const float*)d_in[8];
    const float* a0w = (const float*)d_in[9];
    const float* a0b = (const float*)d_in[10];
    const float* a1w = (const float*)d_in[11];
    const float* a1b = (const float*)d_in[12];
    const float* vw  = (const float*)d_in[13];
    const float* vb  = (const float*)d_in[14];

    int nb = in_sizes[0] / 600;
    if (nb > MAXB) nb = MAXB;

    // unconditional (no static guards per harness rules); not a stream op,
    // safe under graph capture
    cudaFuncSetAttribute(policy_tail,
                         cudaFuncAttributeMaxDynamicSharedMemorySize,
                         B_SMEM_BYTES);

    prep_kernel<<<256, 256>>>(c1w, c2w, fcw, sw);
    conv1_kernel<<<nb, A_THR>>>(obs, c1b, nb);
    int gridB = (nb + BNS - 1) / BNS;
    policy_tail<<<gridB, B_THR, B_SMEM_BYTES>>>(c2b, fcb, sb, a0w, a0b,
                                                a1w, a1b, vw, vb,
                                                (float*)d_out, nb);
}